// round 1
// baseline (speedup 1.0000x reference)
#include <cuda_runtime.h>
#include <cstdint>

// Problem constants
#define BSZ 128
#define SDIM 1024
#define AD 128
#define HH 512
#define KDIM (SDIM + AD)      // 1152 (fused [x_t, u_t] K dimension)
#define OUT_T (HH + 1)        // 513

// Tiling
#define MT 32                 // batch-tile per CTA
#define NT 32                 // n-tile per CTA
#define NCTA_M (BSZ / MT)     // 4
#define NCTA_N (SDIM / NT)    // 32
#define NCTA (NCTA_M * NCTA_N) // 128 CTAs (1 per SM, co-resident)
#define NTHREADS 128
#define KC 128                // k-chunk size
#define NCHUNK (KDIM / KC)    // 9 (8 x-chunks + 1 u-chunk)

// SMEM layout (padded to avoid bank conflicts)
#define WPAD 33
#define XPAD 132
#define WSM_FLOATS (KDIM * WPAD)        // 38016
#define XSM_FLOATS (MT * XPAD)          // 4224
#define SMEM_BYTES ((WSM_FLOATS + 2 * XSM_FLOATS) * 4)  // 185856 B

// Software grid barrier state (persists across graph replays; epochs are
// monotonic, base is re-read each launch).
__device__ unsigned g_arrive[NCTA];
__device__ unsigned g_release;

__device__ __forceinline__ void grid_barrier(unsigned epoch, int bid, int tid)
{
    __syncthreads();
    if (tid == 0) {
        __threadfence();
        *((volatile unsigned*)&g_arrive[bid]) = epoch;
    }
    if (bid == 0) {
        // 128 threads each poll one CTA's slot
        while ((int)(*((volatile unsigned*)&g_arrive[tid]) - epoch) < 0) { }
        __syncthreads();
        if (tid == 0) {
            __threadfence();
            *((volatile unsigned*)&g_release) = epoch;
        }
    } else if (tid == 0) {
        while ((int)(*((volatile unsigned*)&g_release) - epoch) < 0) { }
    }
    __syncthreads();
    __threadfence();
}

__device__ __forceinline__ uint32_t f2tf32(float v)
{
    uint32_t r;
    asm volatile("cvt.rna.tf32.f32 %0, %1;" : "=r"(r) : "f"(v));
    return r;
}

__device__ __forceinline__ void mma_tf32(float* d,
                                         uint32_t a0, uint32_t a1, uint32_t a2, uint32_t a3,
                                         uint32_t b0, uint32_t b1)
{
    asm volatile("mma.sync.aligned.m16n8k8.row.col.f32.tf32.tf32.f32 "
                 "{%0,%1,%2,%3}, {%4,%5,%6,%7}, {%8,%9}, {%0,%1,%2,%3};"
                 : "+f"(d[0]), "+f"(d[1]), "+f"(d[2]), "+f"(d[3])
                 : "r"(a0), "r"(a1), "r"(a2), "r"(a3), "r"(b0), "r"(b1));
}

// Async-load one 32x128 fp32 chunk of [x_t | u_t] into padded smem.
__device__ __forceinline__ void cp_chunk(float* dstsm, const float* __restrict__ out,
                                         const float* __restrict__ u,
                                         int t, int m0, int kc, int tid)
{
#pragma unroll
    for (int j = 0; j < 8; j++) {
        int e = tid + j * NTHREADS;      // 0..1023 float4 slots
        int row = e >> 5;                // 0..31 (local batch row)
        int c4 = e & 31;                 // float4 column within chunk
        const float* src;
        if (kc < 8) {
            // x_t lives at out[:, t, :]
            src = out + ((size_t)(m0 + row) * OUT_T + t) * SDIM + kc * KC + c4 * 4;
        } else {
            src = u + ((size_t)(m0 + row) * HH + t) * AD + c4 * 4;
        }
        uint32_t sdst = (uint32_t)__cvta_generic_to_shared(dstsm + row * XPAD + c4 * 4);
        asm volatile("cp.async.cg.shared.global [%0], [%1], 16;"
                     :: "r"(sdst), "l"(src) : "memory");
    }
}

extern "C" __global__ void __launch_bounds__(NTHREADS, 1)
ssm_persistent_kernel(const float* __restrict__ x0, const float* __restrict__ u,
                      const float* __restrict__ A, const float* __restrict__ Bm,
                      float* __restrict__ out)
{
    extern __shared__ float smem[];
    float* wsm = smem;                         // [KDIM][WPAD] tf32 weight slice
    float* xsm0 = smem + WSM_FLOATS;           // [MT][XPAD]
    float* xsm1 = xsm0 + XSM_FLOATS;

    const int tid = threadIdx.x;
    const int bid = blockIdx.x;
    const int mt = bid & (NCTA_M - 1);
    const int nt = bid >> 2;
    const int m0 = mt * MT;
    const int n0 = nt * NT;
    const int w = tid >> 5;
    const int lane = tid & 31;
    const int wm = w & 1;     // m-strip (16 rows)
    const int wn = w >> 1;    // n-strip (16 cols)

    // Barrier epoch base for this launch (quiescent value from previous launch).
    const unsigned base = *((volatile unsigned*)&g_release);

    // ---- One-time: load fused weight slice W[k][nl] = (k<S ? A[n,k] : B[n,k-S]),
    //      rounded to tf32. Resident in SMEM for the whole rollout. ----
    uint32_t* wsmu = (uint32_t*)wsm;
    for (int i = tid; i < KDIM * NT; i += NTHREADS) {
        int k = i >> 5;
        int nl = i & 31;
        float v = (k < SDIM) ? A[(size_t)(n0 + nl) * SDIM + k]
                             : Bm[(size_t)(n0 + nl) * AD + (k - SDIM)];
        wsmu[k * WPAD + nl] = f2tf32(v);
    }

    // ---- x0 -> out[:, 0, :] (grid-strided float4 copy) ----
    for (int i = bid * NTHREADS + tid; i < BSZ * SDIM / 4; i += NCTA * NTHREADS) {
        int b = i >> 8;          // 256 float4 per batch row
        int s4 = i & 255;
        float4 v = ((const float4*)x0)[i];
        ((float4*)(out + (size_t)b * OUT_T * SDIM))[s4] = v;
    }

    grid_barrier(base + 1, bid, tid);

    // ---- 512 sequential steps ----
    for (int t = 0; t < HH; t++) {
        float d[2][4];
#pragma unroll
        for (int nn = 0; nn < 2; nn++)
#pragma unroll
            for (int q = 0; q < 4; q++) d[nn][q] = 0.0f;

        cp_chunk(xsm0, out, u, t, m0, 0, tid);
        asm volatile("cp.async.commit_group;" ::: "memory");

        for (int kc = 0; kc < NCHUNK; kc++) {
            float* cur = (kc & 1) ? xsm1 : xsm0;
            float* nxt = (kc & 1) ? xsm0 : xsm1;
            if (kc + 1 < NCHUNK) {
                cp_chunk(nxt, out, u, t, m0, kc + 1, tid);
                asm volatile("cp.async.commit_group;" ::: "memory");
                asm volatile("cp.async.wait_group 1;" ::: "memory");
            } else {
                asm volatile("cp.async.wait_group 0;" ::: "memory");
            }
            __syncthreads();

            const uint32_t* xs = (const uint32_t*)cur;
            const int r = wm * 16 + (lane >> 2);
            const int cbase = lane & 3;
            const int nb = wn * 16 + (lane >> 2);
#pragma unroll
            for (int kt = 0; kt < KC / 8; kt++) {
                int c = kt * 8 + cbase;
                uint32_t a0 = f2tf32(__uint_as_float(xs[r * XPAD + c]));
                uint32_t a1 = f2tf32(__uint_as_float(xs[(r + 8) * XPAD + c]));
                uint32_t a2 = f2tf32(__uint_as_float(xs[r * XPAD + c + 4]));
                uint32_t a3 = f2tf32(__uint_as_float(xs[(r + 8) * XPAD + c + 4]));
                int kg = kc * KC + kt * 8 + cbase;
#pragma unroll
                for (int nn = 0; nn < 2; nn++) {
                    uint32_t b0 = wsmu[kg * WPAD + nb + nn * 8];
                    uint32_t b1 = wsmu[(kg + 4) * WPAD + nb + nn * 8];
                    mma_tf32(d[nn], a0, a1, a2, a3, b0, b1);
                }
            }
            __syncthreads();
        }

        // Write x_{t+1} tile to out[:, t+1, :]
        const int rr = m0 + wm * 16 + (lane >> 2);
        const int cc = n0 + wn * 16 + 2 * (lane & 3);
        float* dst = out + (size_t)(t + 1) * SDIM;
#pragma unroll
        for (int nn = 0; nn < 2; nn++) {
            float2 v01 = make_float2(d[nn][0], d[nn][1]);
            float2 v23 = make_float2(d[nn][2], d[nn][3]);
            *(float2*)(dst + (size_t)rr * OUT_T * SDIM + cc + nn * 8) = v01;
            *(float2*)(dst + (size_t)(rr + 8) * OUT_T * SDIM + cc + nn * 8) = v23;
        }

        grid_barrier(base + 2 + t, bid, tid);
    }
}

extern "C" void kernel_launch(void* const* d_in, const int* in_sizes, int n_in,
                              void* d_out, int out_size)
{
    const float* x0 = (const float*)d_in[0];
    const float* u  = (const float*)d_in[1];
    const float* A  = (const float*)d_in[2];
    const float* Bm = (const float*)d_in[3];
    float* out = (float*)d_out;

    // Idempotent, not a stream op — safe under graph capture.
    cudaFuncSetAttribute(ssm_persistent_kernel,
                         cudaFuncAttributeMaxDynamicSharedMemorySize, SMEM_BYTES);

    ssm_persistent_kernel<<<NCTA, NTHREADS, SMEM_BYTES>>>(x0, u, A, Bm, out);
}